// round 1
// baseline (speedup 1.0000x reference)
#include <cuda_runtime.h>
#include <cstdint>
#include <cstddef>

#define VOCAB 100000
#define EMBED 64
#define SENT  20
#define MEM   50
#define BATCH 32
#define HOPS  3

// ---------------- scratch (static device globals; no allocations) ------------
// S[t][b][m][e] : encoding-weighted sentence sums for tables {A, C0, C1, C2}
__device__ float g_S[4][BATCH][MEM][EMBED];     // 1.6 MB
__device__ float g_u[BATCH * EMBED];            // query state (updated by hops)

// ---------------- packed f32x2 helpers (sm_100+) -----------------------------
__device__ __forceinline__ unsigned long long pack2(float lo, float hi) {
    unsigned long long r;
    asm("mov.b64 %0, {%1, %2};" : "=l"(r) : "f"(lo), "f"(hi));
    return r;
}
__device__ __forceinline__ void unpack2(unsigned long long v, float& lo, float& hi) {
    asm("mov.b64 {%0, %1}, %2;" : "=f"(lo), "=f"(hi) : "l"(v));
}
#define FMA2(d, a, b) asm("fma.rn.f32x2 %0, %1, %2, %3;" : "=l"(d) : "l"(a), "l"(b), "l"(d))

// ---------------- kernel 1: gather + position-encoded sums -------------------
// blocks 0..6399: task t*1600 + b*50 + m  ->  g_S[t][b][m][:]
// blocks 6400..6431: query embedding sum  ->  g_u[b][:]
__global__ void __launch_bounds__(EMBED) k_embed_sums(
    const int* __restrict__ stories, const int* __restrict__ queries,
    const float* __restrict__ A, const float* __restrict__ C,
    const float* __restrict__ enc)
{
    const int e = threadIdx.x;
    int task = blockIdx.x;
    if (task < 4 * BATCH * MEM) {
        const int t   = task / (BATCH * MEM);
        const int rem = task % (BATCH * MEM);
        const int b   = rem / MEM;
        const int m   = rem % MEM;
        const float* tab = (t == 0) ? A : (C + (size_t)(t - 1) * VOCAB * EMBED);
        const int* st = stories + (b * MEM + m) * SENT;
        float acc = 0.0f;
        #pragma unroll
        for (int s = 0; s < SENT; ++s) {
            const int idx = __ldg(st + s);
            acc = fmaf(__ldg(tab + (size_t)idx * EMBED + e), __ldg(enc + s * EMBED + e), acc);
        }
        g_S[t][b][m][e] = acc;
    } else {
        const int b = task - 4 * BATCH * MEM;   // 0..31
        const int* qr = queries + b * SENT;
        float acc = 0.0f;
        #pragma unroll
        for (int s = 0; s < SENT; ++s) {
            const int idx = __ldg(qr + s);
            acc = fmaf(__ldg(A + (size_t)idx * EMBED + e), __ldg(enc + s * EMBED + e), acc);
        }
        g_u[b * EMBED + e] = acc;
    }
}

// ---------------- kernel 2: the 3 attention hops -----------------------------
// one block per batch element; 64 threads (thread == embedding dim)
__global__ void __launch_bounds__(EMBED) k_hops()
{
    const int b = blockIdx.x;
    const int e = threadIdx.x;
    __shared__ float u_sh[EMBED];
    __shared__ float d_sh[MEM];

    float u = g_u[b * EMBED + e];
    u_sh[e] = u;
    __syncthreads();

    #pragma unroll
    for (int hop = 0; hop < HOPS; ++hop) {
        const float (*Sm)[EMBED] = g_S[hop][b];       // m for this hop
        const float (*Sc)[EMBED] = g_S[hop + 1][b];   // c for this hop
        // dotted[m] = Sm[m] . u   (threads 0..49, each a full dot; S is L2-hot)
        if (e < MEM) {
            float d = 0.0f;
            #pragma unroll
            for (int ee = 0; ee < EMBED; ++ee)
                d = fmaf(Sm[e][ee], u_sh[ee], d);
            d_sh[e] = d;
        }
        __syncthreads();
        // softmax over MEM (serial on thread 0; tiny)
        if (e == 0) {
            float mx = d_sh[0];
            #pragma unroll
            for (int m = 1; m < MEM; ++m) mx = fmaxf(mx, d_sh[m]);
            float s = 0.0f;
            #pragma unroll
            for (int m = 0; m < MEM; ++m) { float t = __expf(d_sh[m] - mx); d_sh[m] = t; s += t; }
            const float inv = 1.0f / s;
            #pragma unroll
            for (int m = 0; m < MEM; ++m) d_sh[m] *= inv;
        }
        __syncthreads();
        // o[e] = sum_m probs[m] * Sc[m][e];  u += o
        float o = 0.0f;
        #pragma unroll
        for (int m = 0; m < MEM; ++m)
            o = fmaf(d_sh[m], Sc[m][e], o);
        u += o;
        __syncthreads();
        u_sh[e] = u;
        __syncthreads();
    }
    g_u[b * EMBED + e] = u;
}

// ---------------- kernel 3: vocab projection  out = u @ C2^T -----------------
// 128 threads/block, each thread owns 2 consecutive vocab rows x all 32 batches.
// u staged in shared transposed [e][b] so batch pairs are contiguous (LDS.64,
// broadcast across the warp). C2 rows streamed global->register (read once).
// Packed fma.rn.f32x2 halves FMA instruction count vs scalar FFMA.
#define GEMM_T 128
__global__ void __launch_bounds__(GEMM_T) k_vocab_gemm(
    const float* __restrict__ C2, float* __restrict__ out)
{
    __shared__ __align__(16) float us[EMBED * BATCH];   // us[e*32 + b]
    const int tid = threadIdx.x;
    for (int i = tid; i < EMBED * BATCH; i += GEMM_T) {
        const int e = i >> 5, b = i & 31;
        us[i] = g_u[b * EMBED + e];
    }
    __syncthreads();

    const int v0 = (blockIdx.x * GEMM_T + tid) * 2;
    if (v0 >= VOCAB) return;   // VOCAB even, VR=2: rows pairwise valid/invalid

    const float4* cp = (const float4*)(C2 + (size_t)v0 * EMBED);
    unsigned long long acc0[16], acc1[16];
    #pragma unroll
    for (int j = 0; j < 16; ++j) { acc0[j] = 0ull; acc1[j] = 0ull; }

    #pragma unroll 4
    for (int e4 = 0; e4 < 16; ++e4) {
        const float4 ca = __ldg(cp + e4);        // row v0, elems 4e4..4e4+3
        const float4 cb = __ldg(cp + 16 + e4);   // row v0+1
        const float ca_[4] = {ca.x, ca.y, ca.z, ca.w};
        const float cb_[4] = {cb.x, cb.y, cb.z, cb.w};
        #pragma unroll
        for (int k = 0; k < 4; ++k) {
            const int e = e4 * 4 + k;
            const unsigned long long a2 = pack2(ca_[k], ca_[k]);
            const unsigned long long b2 = pack2(cb_[k], cb_[k]);
            const unsigned long long* up = (const unsigned long long*)(us + e * BATCH);
            #pragma unroll
            for (int j = 0; j < 16; ++j) {
                const unsigned long long u2 = up[j];   // (u[2j][e], u[2j+1][e])
                FMA2(acc0[j], a2, u2);
                FMA2(acc1[j], b2, u2);
            }
        }
    }

    #pragma unroll
    for (int j = 0; j < 16; ++j) {
        float a0lo, a0hi, a1lo, a1hi;
        unpack2(acc0[j], a0lo, a0hi);
        unpack2(acc1[j], a1lo, a1hi);
        const int b0 = 2 * j, b1 = 2 * j + 1;
        *(float2*)(out + (size_t)b0 * VOCAB + v0) = make_float2(a0lo, a1lo);
        *(float2*)(out + (size_t)b1 * VOCAB + v0) = make_float2(a0hi, a1hi);
    }
}

// ---------------- launch -----------------------------------------------------
extern "C" void kernel_launch(void* const* d_in, const int* in_sizes, int n_in,
                              void* d_out, int out_size)
{
    // Identify inputs by element count (all distinct) for robustness to order.
    const int* stories  = nullptr;   // 32*50*20 = 32000 int32
    const int* queries  = nullptr;   // 32*20    = 640   int32
    const float* A      = nullptr;   // 100000*64   = 6,400,000 f32
    const float* C      = nullptr;   // 3*100000*64 = 19,200,000 f32
    const float* enc    = nullptr;   // 20*64 = 1280 f32
    for (int i = 0; i < n_in; ++i) {
        switch (in_sizes[i]) {
            case BATCH * MEM * SENT:        stories = (const int*)d_in[i];  break;
            case BATCH * SENT:              queries = (const int*)d_in[i];  break;
            case VOCAB * EMBED:             A       = (const float*)d_in[i]; break;
            case HOPS * VOCAB * EMBED:      C       = (const float*)d_in[i]; break;
            case SENT * EMBED:              enc     = (const float*)d_in[i]; break;
            default: break;
        }
    }
    float* out = (float*)d_out;
    const float* C2 = C + (size_t)(HOPS - 1) * VOCAB * EMBED;

    // 1) all gathers + encoding-weighted sums (S tensors for every hop + u0)
    k_embed_sums<<<4 * BATCH * MEM + BATCH, EMBED>>>(stories, queries, A, C, enc);
    // 2) three attention hops (sequentially dependent, tiny)
    k_hops<<<BATCH, EMBED>>>();
    // 3) vocab projection
    const int gblocks = (VOCAB + 2 * GEMM_T - 1) / (2 * GEMM_T);   // 391
    k_vocab_gemm<<<gblocks, GEMM_T>>>(C2, out);
    (void)out_size;
}

// round 5
// speedup vs baseline: 1.3513x; 1.3513x over previous
#include <cuda_runtime.h>
#include <cstdint>
#include <cstddef>

#define VOCAB 100000
#define EMBED 64
#define SENT  20
#define MEM   50
#define BATCH 32
#define HOPS  3

// ---------------- scratch (static device globals; no allocations) ------------
__device__ float g_S[4][BATCH][MEM][EMBED];     // encoding-weighted sums, 1.6 MB
__device__ float g_u[BATCH * EMBED];            // u state [b][e]
__device__ float g_uT[EMBED * BATCH];           // u transposed [e][b] for GEMM

// ---------------- packed f32x2 helpers (sm_100+) -----------------------------
__device__ __forceinline__ unsigned long long pack2(float lo, float hi) {
    unsigned long long r;
    asm("mov.b64 %0, {%1, %2};" : "=l"(r) : "f"(lo), "f"(hi));
    return r;
}
__device__ __forceinline__ void unpack2(unsigned long long v, float& lo, float& hi) {
    asm("mov.b64 {%0, %1}, %2;" : "=f"(lo), "=f"(hi) : "l"(v));
}
#define FMA2(d, a, b) asm("fma.rn.f32x2 %0, %1, %2, %3;" : "=l"(d) : "l"(a), "l"(b), "l"(d))

// ---------------- kernel 1: gather + position-encoded sums -------------------
// 256 threads/block = 16 tasks x 16 threads; each thread owns one float4 of E.
// Blocks 0..399: story tasks (block/100 selects table {A,C0,C1,C2}; 16 rows of
// stories per block, contiguous). Blocks 400..401: query tasks (table A).
__global__ void __launch_bounds__(256) k_embed_sums(
    const int* __restrict__ stories, const int* __restrict__ queries,
    const float* __restrict__ A, const float* __restrict__ C,
    const float* __restrict__ enc)
{
    __shared__ __align__(16) float4 enc4[SENT * 16];   // enc as float4 [s][f4]
    __shared__ int idx_sh[16 * SENT];                  // 16 tasks x 20 indices

    const int tid = threadIdx.x;
    const int blk = blockIdx.x;
    const bool is_q = (blk >= 400);

    for (int i = tid; i < SENT * 16; i += 256)
        enc4[i] = __ldg(((const float4*)enc) + i);

    const int* src = is_q ? (queries + (blk - 400) * 16 * SENT)
                          : (stories + (blk % 100) * 16 * SENT);
    for (int i = tid; i < 16 * SENT; i += 256)
        idx_sh[i] = __ldg(src + i);
    __syncthreads();

    const int tl  = tid >> 4;   // task in block (0..15)
    const int f4i = tid & 15;   // float4 index in E (0..15)

    const float* tab;
    int t = 0;
    if (is_q) {
        tab = A;
    } else {
        t = blk / 100;
        tab = (t == 0) ? A : (C + (size_t)(t - 1) * VOCAB * EMBED);
    }

    float4 acc = make_float4(0.f, 0.f, 0.f, 0.f);
    #pragma unroll
    for (int s = 0; s < SENT; ++s) {
        const int idx = idx_sh[tl * SENT + s];
        const float4 w  = __ldg((const float4*)(tab + (size_t)idx * EMBED) + f4i);
        const float4 en = enc4[s * 16 + f4i];
        acc.x = fmaf(w.x, en.x, acc.x);
        acc.y = fmaf(w.y, en.y, acc.y);
        acc.z = fmaf(w.z, en.z, acc.z);
        acc.w = fmaf(w.w, en.w, acc.w);
    }

    if (is_q) {
        const int b = (blk - 400) * 16 + tl;          // 0..31
        ((float4*)(g_u + b * EMBED))[f4i] = acc;
    } else {
        const int rem = (blk % 100) * 16 + tl;        // b*MEM + m, 0..1599
        ((float4*)(&g_S[t][0][0][0] + (size_t)rem * EMBED))[f4i] = acc;
    }
}

// ---------------- kernel 2: the 3 attention hops -----------------------------
// One block per batch. All four S[.][b] tiles cached in shared (pitch 65 to
// kill bank conflicts), warp-parallel softmax, 4-thread-per-m dots.
#define SP 65   // shared pitch for S rows
__global__ void __launch_bounds__(256) k_hops()
{
    const int b   = blockIdx.x;
    const int tid = threadIdx.x;
    __shared__ float S_sh[4 * MEM * SP];   // 52 KB
    __shared__ float u_sh[EMBED];
    __shared__ float d_sh[MEM];

    // coalesced load of the 4 S tiles for this batch, re-pitched to 65
    #pragma unroll
    for (int t = 0; t < 4; ++t) {
        const float4* src = (const float4*)(&g_S[t][b][0][0]);   // 800 float4
        float* dst = S_sh + t * MEM * SP;
        for (int i = tid; i < MEM * 16; i += 256) {
            const float4 v = src[i];
            const int m = i >> 4, e0 = (i & 15) * 4;
            float* p = dst + m * SP + e0;
            p[0] = v.x; p[1] = v.y; p[2] = v.z; p[3] = v.w;
        }
    }
    if (tid < EMBED) u_sh[tid] = g_u[b * EMBED + tid];
    __syncthreads();

    #pragma unroll
    for (int hop = 0; hop < HOPS; ++hop) {
        // dotted[m] = S[hop][m] . u  — 4 threads per m, shuffle-combined
        {
            const int m = tid >> 2, q = tid & 3;       // m up to 63 (garbage ok)
            const float* Sm = S_sh + hop * MEM * SP + m * SP;
            float d = 0.f;
            #pragma unroll
            for (int k = 0; k < 16; ++k) {
                const int e = q + 4 * k;
                d = fmaf(Sm[e], u_sh[e], d);
            }
            d += __shfl_xor_sync(0xffffffffu, d, 1);
            d += __shfl_xor_sync(0xffffffffu, d, 2);
            if (q == 0 && m < MEM) d_sh[m] = d;
        }
        __syncthreads();
        // softmax over MEM=50 on warp 0
        if (tid < 32) {
            const float v1 = d_sh[tid];
            const float v2 = (tid < MEM - 32) ? d_sh[tid + 32] : -3.4e38f;
            float mx = fmaxf(v1, v2);
            #pragma unroll
            for (int off = 16; off; off >>= 1)
                mx = fmaxf(mx, __shfl_xor_sync(0xffffffffu, mx, off));
            const float e1 = __expf(v1 - mx);
            const float e2 = (tid < MEM - 32) ? __expf(v2 - mx) : 0.f;
            float s = e1 + e2;
            #pragma unroll
            for (int off = 16; off; off >>= 1)
                s += __shfl_xor_sync(0xffffffffu, s, off);
            const float inv = 1.f / s;
            d_sh[tid] = e1 * inv;
            if (tid < MEM - 32) d_sh[tid + 32] = e2 * inv;
        }
        __syncthreads();
        // u += sum_m probs[m] * S[hop+1][m][e]
        if (tid < EMBED) {
            const float* Sc = S_sh + (hop + 1) * MEM * SP + tid;
            float o = 0.f;
            #pragma unroll
            for (int m = 0; m < MEM; ++m)
                o = fmaf(d_sh[m], Sc[m * SP], o);
            u_sh[tid] += o;
        }
        __syncthreads();
    }

    if (tid < EMBED) {
        const float u = u_sh[tid];
        g_u[b * EMBED + tid] = u;
        g_uT[tid * BATCH + b] = u;     // transposed copy for the GEMM
    }
}

// ---------------- kernel 3: vocab projection  out = u @ C2^T -----------------
// 64 threads/block, 128 vocab rows/block staged in shared (coalesced float4
// global loads, pitch 68 -> max 4-way LDS conflict). Each thread owns rows
// tid and tid+64 x all 32 batches; u read as broadcast LDS.128 from shared.
#define GT 64
#define TILE_V 128
__global__ void __launch_bounds__(GT) k_vocab_gemm(
    const float* __restrict__ C2, float* __restrict__ out)
{
    __shared__ __align__(16) float tile[TILE_V * 68];   // 34.8 KB
    __shared__ __align__(16) float us[EMBED * BATCH];   // [e][b], 8 KB
    const int tid = threadIdx.x;
    const long gbase = (long)blockIdx.x * TILE_V;

    #pragma unroll
    for (int i = 0; i < (EMBED * BATCH / 4) / GT; ++i)
        ((float4*)us)[tid + i * GT] = __ldg(((const float4*)g_uT) + tid + i * GT);

    for (int i = tid; i < TILE_V * 16; i += GT) {
        const int row = i >> 4, c = i & 15;
        float4 v = make_float4(0.f, 0.f, 0.f, 0.f);
        if (gbase + row < VOCAB)
            v = __ldg((const float4*)(C2 + (gbase + row) * EMBED) + c);
        *(float4*)&tile[row * 68 + c * 4] = v;
    }
    __syncthreads();

    const float* rA = tile + tid * 68;
    const float* rB = tile + (tid + 64) * 68;
    unsigned long long acc0[16], acc1[16];
    #pragma unroll
    for (int j = 0; j < 16; ++j) { acc0[j] = 0ull; acc1[j] = 0ull; }

    #pragma unroll 4
    for (int e4 = 0; e4 < 16; ++e4) {
        const float4 cA = *(const float4*)(rA + e4 * 4);
        const float4 cB = *(const float4*)(rB + e4 * 4);
        const float a_[4] = {cA.x, cA.y, cA.z, cA.w};
        const float b_[4] = {cB.x, cB.y, cB.z, cB.w};
        #pragma unroll
        for (int k = 0; k < 4; ++k) {
            const int e = e4 * 4 + k;
            const unsigned long long a2 = pack2(a_[k], a_[k]);
            const unsigned long long b2 = pack2(b_[k], b_[k]);
            const ulonglong2* up = (const ulonglong2*)(us + e * BATCH);
            #pragma unroll
            for (int j = 0; j < 8; ++j) {
                const ulonglong2 uu = up[j];       // batches 4j..4j+3 (paired)
                FMA2(acc0[2 * j],     a2, uu.x);
                FMA2(acc0[2 * j + 1], a2, uu.y);
                FMA2(acc1[2 * j],     b2, uu.x);
                FMA2(acc1[2 * j + 1], b2, uu.y);
            }
        }
    }

    const long vA = gbase + tid;
    const long vB = gbase + 64 + tid;
    #pragma unroll
    for (int j = 0; j < 16; ++j) {
        float lo0, hi0, lo1, hi1;
        unpack2(acc0[j], lo0, hi0);
        unpack2(acc1[j], lo1, hi1);
        const long b0 = 2 * j, b1 = 2 * j + 1;
        if (vA < VOCAB) { out[b0 * VOCAB + vA] = lo0; out[b1 * VOCAB + vA] = hi0; }
        if (vB < VOCAB) { out[b0 * VOCAB + vB] = lo1; out[b1 * VOCAB + vB] = hi1; }
    }
}

// ---------------- launch -----------------------------------------------------
extern "C" void kernel_launch(void* const* d_in, const int* in_sizes, int n_in,
                              void* d_out, int out_size)
{
    const int* stories = nullptr;
    const int* queries = nullptr;
    const float* A = nullptr;
    const float* C = nullptr;
    const float* enc = nullptr;
    for (int i = 0; i < n_in; ++i) {
        switch (in_sizes[i]) {
            case BATCH * MEM * SENT:   stories = (const int*)d_in[i];   break;
            case BATCH * SENT:         queries = (const int*)d_in[i];   break;
            case VOCAB * EMBED:        A       = (const float*)d_in[i]; break;
            case HOPS * VOCAB * EMBED: C       = (const float*)d_in[i]; break;
            case SENT * EMBED:         enc     = (const float*)d_in[i]; break;
            default: break;
        }
    }
    float* out = (float*)d_out;
    const float* C2 = C + (size_t)(HOPS - 1) * VOCAB * EMBED;

    k_embed_sums<<<402, 256>>>(stories, queries, A, C, enc);
    k_hops<<<BATCH, 256>>>();
    k_vocab_gemm<<<(VOCAB + TILE_V - 1) / TILE_V, GT>>>(C2, out);
    (void)out_size;
}